// round 8
// baseline (speedup 1.0000x reference)
#include <cuda_runtime.h>
#include <math.h>
#include <float.h>

#define NW   1024
#define NOCT 12
#define NCOL 16
#define NB   8

// ---- static device scratch ----
__device__ float         g_hxn[NOCT * NW];
__device__ unsigned      g_nmin, g_nmax, g_omin, g_omax;
__device__ unsigned char g_idx[NW * NW];

__constant__ float c_pw[NOCT] = {
    1.0f, 1.5f, 2.25f, 3.375f, 5.0625f, 7.59375f, 11.390625f,
    17.0859375f, 25.62890625f, 38.443359375f, 57.6650390625f, 86.49755859375f
};

// ---- packed f32x2 / bit helpers ----
__device__ __forceinline__ void fma2(unsigned long long& d, unsigned long long a, unsigned long long b) {
    asm("fma.rn.f32x2 %0, %1, %2, %0;" : "+l"(d) : "l"(a), "l"(b));
}
__device__ __forceinline__ unsigned long long fmascale2(unsigned long long d, unsigned long long a, unsigned long long b) {
    asm("fma.rn.f32x2 %0, %0, %1, %2;" : "+l"(d) : "l"(a), "l"(b)); return d;
}
__device__ __forceinline__ unsigned long long add2(unsigned long long a, unsigned long long b) {
    unsigned long long r; asm("add.rn.f32x2 %0, %1, %2;" : "=l"(r) : "l"(a), "l"(b)); return r;
}
__device__ __forceinline__ unsigned long long pack2(float f) {
    unsigned long long r; asm("mov.b64 %0, {%1, %1};" : "=l"(r) : "f"(f)); return r;
}
__device__ __forceinline__ unsigned long long pkbits(unsigned a, unsigned b) {
    unsigned long long r; asm("mov.b64 %0, {%1, %2};" : "=l"(r) : "r"(a), "r"(b)); return r;
}
__device__ __forceinline__ void unpack2(unsigned long long v, float& a, float& b) {
    asm("mov.b64 {%0, %1}, %2;" : "=f"(a), "=f"(b) : "l"(v));
}
__device__ __forceinline__ unsigned prmtf(unsigned a, unsigned sel) {
    unsigned r; asm("prmt.b32 %0, %1, %2, %3;" : "=r"(r) : "r"(a), "r"(0x4B000000u), "r"(sel)); return r;
}

// One block per octave; also inits the global min/max cells.
__global__ void k_octaves() {
    int i = threadIdx.x;
    int o = blockIdx.x;
    if (o == 0 && i == 0) {
        g_nmin = 0x7f7fffffu; g_nmax = 0u;
        g_omin = 0x7f7fffffu; g_omax = 0u;
    }
    __shared__ float smn[32], smx[32];

    float xi = __fmul_rn((float)i, 1.0f / 1023.0f);
    float scale = (float)((double)(320 << o) * 3.14159265358979323846);
    float arg = __fmul_rn(xi, scale);
    float s = (float)sin((double)arg);

    float mn = s, mx = s;
    #pragma unroll
    for (int off = 16; off; off >>= 1) {
        mn = fminf(mn, __shfl_xor_sync(0xffffffffu, mn, off));
        mx = fmaxf(mx, __shfl_xor_sync(0xffffffffu, mx, off));
    }
    if ((i & 31) == 0) { smn[i >> 5] = mn; smx[i >> 5] = mx; }
    __syncthreads();
    if (i < 32) {
        mn = smn[i]; mx = smx[i];
        #pragma unroll
        for (int off = 16; off; off >>= 1) {
            mn = fminf(mn, __shfl_xor_sync(0xffffffffu, mn, off));
            mx = fmaxf(mx, __shfl_xor_sync(0xffffffffu, mx, off));
        }
        if (i == 0) { smn[0] = mn; smx[0] = mx; }
    }
    __syncthreads();
    g_hxn[o * NW + i] = __fdiv_rn(__fsub_rn(s, smn[0]), __fsub_rn(smx[0], smn[0]));
}

// 4 pixels/thread -> global noise min/max
__global__ void k_nminmax() {
    int g = blockIdx.x * 256 + threadIdx.x;
    int i = g >> 8, j0 = (g & 255) << 2;
    float n0 = 0.f, n1 = 0.f, n2 = 0.f, n3 = 0.f;
    #pragma unroll
    for (int o = 0; o < NOCT; o++) {
        float a = __ldg(&g_hxn[o * NW + i]);
        float4 b = __ldg((const float4*)&g_hxn[o * NW + j0]);
        float p = c_pw[o];
        n0 = __fadd_rn(n0, __fmul_rn(__fadd_rn(a, b.x), p));
        n1 = __fadd_rn(n1, __fmul_rn(__fadd_rn(a, b.y), p));
        n2 = __fadd_rn(n2, __fmul_rn(__fadd_rn(a, b.z), p));
        n3 = __fadd_rn(n3, __fmul_rn(__fadd_rn(a, b.w), p));
    }
    float mn = fminf(fminf(n0, n1), fminf(n2, n3));
    float mx = fmaxf(fmaxf(n0, n1), fmaxf(n2, n3));
    #pragma unroll
    for (int off = 16; off; off >>= 1) {
        mn = fminf(mn, __shfl_xor_sync(0xffffffffu, mn, off));
        mx = fmaxf(mx, __shfl_xor_sync(0xffffffffu, mx, off));
    }
    __shared__ float smn[8], smx[8];
    int lane = threadIdx.x & 31, w = threadIdx.x >> 5;
    if (lane == 0) { smn[w] = mn; smx[w] = mx; }
    __syncthreads();
    if (threadIdx.x == 0) {
        mn = smn[0]; mx = smx[0];
        #pragma unroll
        for (int q = 1; q < 8; q++) { mn = fminf(mn, smn[q]); mx = fmaxf(mx, smx[q]); }
        atomicMin(&g_nmin, __float_as_uint(mn));
        atomicMax(&g_nmax, __float_as_uint(mx));
    }
}

// 4 pixels/thread: noise -> palette index, uchar4 stores
__global__ void k_makeidx() {
    int g = blockIdx.x * 256 + threadIdx.x;
    int i = g >> 8, j0 = (g & 255) << 2;
    float n0 = 0.f, n1 = 0.f, n2 = 0.f, n3 = 0.f;
    #pragma unroll
    for (int o = 0; o < NOCT; o++) {
        float a = __ldg(&g_hxn[o * NW + i]);
        float4 b = __ldg((const float4*)&g_hxn[o * NW + j0]);
        float p = c_pw[o];
        n0 = __fadd_rn(n0, __fmul_rn(__fadd_rn(a, b.x), p));
        n1 = __fadd_rn(n1, __fmul_rn(__fadd_rn(a, b.y), p));
        n2 = __fadd_rn(n2, __fmul_rn(__fadd_rn(a, b.z), p));
        n3 = __fadd_rn(n3, __fmul_rn(__fadd_rn(a, b.w), p));
    }
    float mn = __uint_as_float(g_nmin);
    float mx = __uint_as_float(g_nmax);
    float d = __fsub_rn(mx, mn);
    uchar4 v;
    v.x = (unsigned char)(int)rintf(__fmul_rn(__fdiv_rn(__fsub_rn(n0, mn), d), 15.0f));
    v.y = (unsigned char)(int)rintf(__fmul_rn(__fdiv_rn(__fsub_rn(n1, mn), d), 15.0f));
    v.z = (unsigned char)(int)rintf(__fmul_rn(__fdiv_rn(__fsub_rn(n2, mn), d), 15.0f));
    v.w = (unsigned char)(int)rintf(__fmul_rn(__fdiv_rn(__fsub_rn(n3, mn), d), 15.0f));
    ((uchar4*)g_idx)[g] = v;
}

// Separable count-space box blur; dot phase transposed (thread = 1 batch x 8 pixels).
template <bool WRITE>
__global__ void __launch_bounds__(256) k_blur(const float* __restrict__ colors,
                                              float* __restrict__ out) {
    __shared__ unsigned char tile[12][36];
    __shared__ __align__(16) float colB4[NB * 17 * 4];   // [b][k] float4, stride 17 -> no conflicts
    __shared__ __align__(16) unsigned char sbuf[24960];  // union: vcnt+hbuf | stage3
    __shared__ float smn[8], smx[8];

    typedef uint4 (*vcnt_t)[40];
    vcnt_t vcnt = (vcnt_t)sbuf;                       // [8][40] uint4 @ 0..5120
    uint4* hbufp = (uint4*)(sbuf + 5120);             // 287 uint4 (padded idx p + p/8)
    float* stage3 = (float*)sbuf;                     // 24 * 260 floats (WRITE only)

    int tx = threadIdx.x, ty = threadIdx.y;           // blockDim = (32, 8)
    int t = ty * 32 + tx;

    // palette -> smem: colB4[(b*17 + k)*4 + c], c<3 real, c=3 pad
    for (int idx = t; idx < NB * NCOL * 4; idx += 256) {
        int b = idx >> 6, rem = idx & 63, k = rem >> 2, c = rem & 3;
        colB4[(b * 17 + k) * 4 + c] = (c < 3) ? colors[b * 48 + k * 3 + c] : 0.0f;
    }

    int bi0 = blockIdx.y * 8, bj0 = blockIdx.x * 32;
    for (int q = t; q < 12 * 36; q += 256) {
        int r = q / 36, cc = q % 36;
        int gi = bi0 + r - 2, gj = bj0 + cc - 2;
        unsigned char v = 16;  // border sentinel: no count
        if ((unsigned)gi < (unsigned)NW && (unsigned)gj < (unsigned)NW)
            v = g_idx[gi * NW + gj];
        tile[r][cc] = v;
    }
    __syncthreads();

    // Phase 2: vertical 5-tap packed counts (288 entries, u8 fields in 4 x u32)
    for (int e = t; e < 8 * 36; e += 256) {
        int r = e / 36, c = e % 36;
        unsigned h0 = 0, h1 = 0, h2 = 0, h3 = 0;
        #pragma unroll
        for (int dy = 0; dy < 5; dy++) {
            int k = tile[r + dy][c];
            unsigned one = 1u << ((k & 3) * 8);
            unsigned w = (unsigned)k >> 2;
            h0 += (w == 0) ? one : 0u;
            h1 += (w == 1) ? one : 0u;
            h2 += (w == 2) ? one : 0u;
            h3 += (w == 3) ? one : 0u;
        }
        vcnt[r][c] = make_uint4(h0, h1, h2, h3);
    }
    __syncthreads();

    // Phase 3: horizontal 5-tap sum for own pixel -> hbuf (padded: idx = p + p/8)
    {
        uint4 h = vcnt[ty][tx];
        #pragma unroll
        for (int dx = 1; dx < 5; dx++) {
            uint4 v = vcnt[ty][tx + dx];
            h.x += v.x; h.y += v.y; h.z += v.z; h.w += v.w;
        }
        hbufp[t + (t >> 3)] = h;
    }
    __syncthreads();

    // Phase 4 (dot): thread = batch b = t&7, pixel group pg = t>>3 (8 pixels)
    int b = t & 7, pg = t >> 3;
    const float4* colp = (const float4*)&colB4[b * 17 * 4];
    const unsigned long long bias2 = pack2(-8388608.0f);

    float lmn = FLT_MAX, lmx = 0.0f;                 // MINMAX path
    float mnv = 0.f, inv = 0.f;
    unsigned long long kwi2 = 0, off2 = 0;
    if (WRITE) {
        mnv = __uint_as_float(g_omin);
        float mxv = __uint_as_float(g_omax);
        inv = 1.0f / (mxv - mnv);
        kwi2 = pack2(0.04f * inv);
        off2 = pack2(-mnv * inv);
    }

    float vals[2][12];   // [half][pair*6 ... ] unpacked results (WRITE path)
    #pragma unroll
    for (int half = 0; half < 2; half++) {
        uint4 hh0 = hbufp[pg * 9 + half * 4 + 0];
        uint4 hh1 = hbufp[pg * 9 + half * 4 + 1];
        uint4 hh2 = hbufp[pg * 9 + half * 4 + 2];
        uint4 hh3 = hbufp[pg * 9 + half * 4 + 3];
        unsigned long long acc[6];
        #pragma unroll
        for (int q = 0; q < 6; q++) acc[q] = 0ull;

        #pragma unroll
        for (int k = 0; k < NCOL; k++) {
            float4 col = colp[k];
            unsigned long long cx = pack2(col.x);
            unsigned long long cy = pack2(col.y);
            unsigned long long cz = pack2(col.z);
            unsigned sel = 0x7440u | (unsigned)(k & 3);
            unsigned w0, w1, w2, w3;
            if ((k >> 2) == 0)      { w0 = hh0.x; w1 = hh1.x; w2 = hh2.x; w3 = hh3.x; }
            else if ((k >> 2) == 1) { w0 = hh0.y; w1 = hh1.y; w2 = hh2.y; w3 = hh3.y; }
            else if ((k >> 2) == 2) { w0 = hh0.z; w1 = hh1.z; w2 = hh2.z; w3 = hh3.z; }
            else                    { w0 = hh0.w; w1 = hh1.w; w2 = hh2.w; w3 = hh3.w; }
            unsigned long long c01 = add2(pkbits(prmtf(w0, sel), prmtf(w1, sel)), bias2);
            unsigned long long c23 = add2(pkbits(prmtf(w2, sel), prmtf(w3, sel)), bias2);
            fma2(acc[0], c01, cx); fma2(acc[1], c01, cy); fma2(acc[2], c01, cz);
            fma2(acc[3], c23, cx); fma2(acc[4], c23, cy); fma2(acc[5], c23, cz);
        }

        if (!WRITE) {
            #pragma unroll
            for (int q = 0; q < 6; q++) {
                float a, bb; unpack2(acc[q], a, bb);
                lmn = fminf(lmn, fminf(a, bb));
                lmx = fmaxf(lmx, fmaxf(a, bb));
            }
        } else {
            #pragma unroll
            for (int q = 0; q < 6; q++) {
                unsigned long long v = fmascale2(acc[q], kwi2, off2);
                unpack2(v, vals[half][2 * q], vals[half][2 * q + 1]);
            }
        }
    }

    if (!WRITE) {
        lmn *= 0.04f; lmx *= 0.04f;
        #pragma unroll
        for (int off = 16; off; off >>= 1) {
            lmn = fminf(lmn, __shfl_xor_sync(0xffffffffu, lmn, off));
            lmx = fmaxf(lmx, __shfl_xor_sync(0xffffffffu, lmx, off));
        }
        int lane = t & 31, w = t >> 5;
        if (lane == 0) { smn[w] = lmn; smx[w] = lmx; }
        __syncthreads();
        if (t == 0) {
            lmn = smn[0]; lmx = smx[0];
            #pragma unroll
            for (int q = 1; q < 8; q++) { lmn = fminf(lmn, smn[q]); lmx = fmaxf(lmx, smx[q]); }
            atomicMin(&g_omin, __float_as_uint(lmn));
            atomicMax(&g_omax, __float_as_uint(lmx));
        }
    } else {
        __syncthreads();   // all hbuf/vcnt reads done before stage3 overwrites sbuf
        #pragma unroll
        for (int half = 0; half < 2; half++)
            #pragma unroll
            for (int q = 0; q < 6; q++) {
                int pair = q / 3, ch = q % 3;
                int p0 = pg * 8 + half * 4 + pair * 2;
                stage3[(b * 3 + ch) * 260 + p0]     = vals[half][2 * q];
                stage3[(b * 3 + ch) * 260 + p0 + 1] = vals[half][2 * q + 1];
            }
        __syncthreads();
        // coalesced output: 1536 float4 chunks, 6 per thread
        #pragma unroll
        for (int s = 0; s < 6; s++) {
            int m2 = t + 256 * s;
            int ob = m2 / 192;
            int rm = m2 % 192;
            int r = rm / 24, c4 = rm % 24;
            float4 v;
            float* vp = (float*)&v;
            #pragma unroll
            for (int u = 0; u < 4; u++) {
                int f = 4 * c4 + u;
                vp[u] = stage3[(ob * 3 + (f % 3)) * 260 + r * 32 + (f / 3)];
            }
            long long base = (((long long)ob * NW + (bi0 + r)) * NW + bj0) * 3 + 4 * c4;
            *(float4*)&out[base] = v;
        }
    }
}

extern "C" void kernel_launch(void* const* d_in, const int* in_sizes, int n_in,
                              void* d_out, int out_size) {
    (void)in_sizes; (void)n_in; (void)out_size;
    const float* colors = (const float*)d_in[0];
    float* out = (float*)d_out;

    k_octaves<<<NOCT, NW>>>();
    k_nminmax<<<(NW * NW / 4) / 256, 256>>>();
    k_makeidx<<<(NW * NW / 4) / 256, 256>>>();

    dim3 blk(32, 8);
    dim3 grd(NW / 32, NW / 8);
    k_blur<false><<<grd, blk>>>(colors, nullptr);
    k_blur<true><<<grd, blk>>>(colors, out);
}

// round 9
// speedup vs baseline: 1.0308x; 1.0308x over previous
#include <cuda_runtime.h>
#include <math.h>
#include <float.h>

#define NW   1024
#define NOCT 12
#define NCOL 16
#define NB   8

// ---- static device scratch ----
__device__ float         g_hxn[NOCT * NW];
__device__ unsigned      g_nmin, g_nmax, g_omin, g_omax;
__device__ unsigned char g_idx[NW * NW];

__constant__ float c_pw[NOCT] = {
    1.0f, 1.5f, 2.25f, 3.375f, 5.0625f, 7.59375f, 11.390625f,
    17.0859375f, 25.62890625f, 38.443359375f, 57.6650390625f, 86.49755859375f
};

// ---- packed f32x2 / bit helpers ----
__device__ __forceinline__ void fma2(unsigned long long& d, unsigned long long a, unsigned long long b) {
    asm("fma.rn.f32x2 %0, %1, %2, %0;" : "+l"(d) : "l"(a), "l"(b));
}
__device__ __forceinline__ unsigned long long fmascale2(unsigned long long d, unsigned long long a, unsigned long long b) {
    asm("fma.rn.f32x2 %0, %0, %1, %2;" : "+l"(d) : "l"(a), "l"(b)); return d;
}
__device__ __forceinline__ unsigned long long add2(unsigned long long a, unsigned long long b) {
    unsigned long long r; asm("add.rn.f32x2 %0, %1, %2;" : "=l"(r) : "l"(a), "l"(b)); return r;
}
__device__ __forceinline__ unsigned long long pack2(float f) {
    unsigned long long r; asm("mov.b64 %0, {%1, %1};" : "=l"(r) : "f"(f)); return r;
}
__device__ __forceinline__ unsigned long long pkbits(unsigned a, unsigned b) {
    unsigned long long r; asm("mov.b64 %0, {%1, %2};" : "=l"(r) : "r"(a), "r"(b)); return r;
}
__device__ __forceinline__ void unpack2(unsigned long long v, float& a, float& b) {
    asm("mov.b64 {%0, %1}, %2;" : "=f"(a), "=f"(b) : "l"(v));
}
__device__ __forceinline__ unsigned prmtf(unsigned a, unsigned sel) {
    unsigned r; asm("prmt.b32 %0, %1, %2, %3;" : "=r"(r) : "r"(a), "r"(0x4B000000u), "r"(sel)); return r;
}

// One block per octave; also inits the global min/max cells.
__global__ void k_octaves() {
    int i = threadIdx.x;
    int o = blockIdx.x;
    if (o == 0 && i == 0) {
        g_nmin = 0x7f7fffffu; g_nmax = 0u;
        g_omin = 0x7f7fffffu; g_omax = 0u;
    }
    __shared__ float smn[32], smx[32];

    float xi = __fmul_rn((float)i, 1.0f / 1023.0f);
    float scale = (float)((double)(320 << o) * 3.14159265358979323846);
    float arg = __fmul_rn(xi, scale);
    float s = (float)sin((double)arg);

    float mn = s, mx = s;
    #pragma unroll
    for (int off = 16; off; off >>= 1) {
        mn = fminf(mn, __shfl_xor_sync(0xffffffffu, mn, off));
        mx = fmaxf(mx, __shfl_xor_sync(0xffffffffu, mx, off));
    }
    if ((i & 31) == 0) { smn[i >> 5] = mn; smx[i >> 5] = mx; }
    __syncthreads();
    if (i < 32) {
        mn = smn[i]; mx = smx[i];
        #pragma unroll
        for (int off = 16; off; off >>= 1) {
            mn = fminf(mn, __shfl_xor_sync(0xffffffffu, mn, off));
            mx = fmaxf(mx, __shfl_xor_sync(0xffffffffu, mx, off));
        }
        if (i == 0) { smn[0] = mn; smx[0] = mx; }
    }
    __syncthreads();
    g_hxn[o * NW + i] = __fdiv_rn(__fsub_rn(s, smn[0]), __fsub_rn(smx[0], smn[0]));
}

// 4 pixels/thread -> global noise min/max
__global__ void k_nminmax() {
    int g = blockIdx.x * 256 + threadIdx.x;
    int i = g >> 8, j0 = (g & 255) << 2;
    float n0 = 0.f, n1 = 0.f, n2 = 0.f, n3 = 0.f;
    #pragma unroll
    for (int o = 0; o < NOCT; o++) {
        float a = __ldg(&g_hxn[o * NW + i]);
        float4 b = __ldg((const float4*)&g_hxn[o * NW + j0]);
        float p = c_pw[o];
        n0 = __fadd_rn(n0, __fmul_rn(__fadd_rn(a, b.x), p));
        n1 = __fadd_rn(n1, __fmul_rn(__fadd_rn(a, b.y), p));
        n2 = __fadd_rn(n2, __fmul_rn(__fadd_rn(a, b.z), p));
        n3 = __fadd_rn(n3, __fmul_rn(__fadd_rn(a, b.w), p));
    }
    float mn = fminf(fminf(n0, n1), fminf(n2, n3));
    float mx = fmaxf(fmaxf(n0, n1), fmaxf(n2, n3));
    #pragma unroll
    for (int off = 16; off; off >>= 1) {
        mn = fminf(mn, __shfl_xor_sync(0xffffffffu, mn, off));
        mx = fmaxf(mx, __shfl_xor_sync(0xffffffffu, mx, off));
    }
    __shared__ float smn[8], smx[8];
    int lane = threadIdx.x & 31, w = threadIdx.x >> 5;
    if (lane == 0) { smn[w] = mn; smx[w] = mx; }
    __syncthreads();
    if (threadIdx.x == 0) {
        mn = smn[0]; mx = smx[0];
        #pragma unroll
        for (int q = 1; q < 8; q++) { mn = fminf(mn, smn[q]); mx = fmaxf(mx, smx[q]); }
        atomicMin(&g_nmin, __float_as_uint(mn));
        atomicMax(&g_nmax, __float_as_uint(mx));
    }
}

// 4 pixels/thread: noise -> palette index, uchar4 stores
__global__ void k_makeidx() {
    int g = blockIdx.x * 256 + threadIdx.x;
    int i = g >> 8, j0 = (g & 255) << 2;
    float n0 = 0.f, n1 = 0.f, n2 = 0.f, n3 = 0.f;
    #pragma unroll
    for (int o = 0; o < NOCT; o++) {
        float a = __ldg(&g_hxn[o * NW + i]);
        float4 b = __ldg((const float4*)&g_hxn[o * NW + j0]);
        float p = c_pw[o];
        n0 = __fadd_rn(n0, __fmul_rn(__fadd_rn(a, b.x), p));
        n1 = __fadd_rn(n1, __fmul_rn(__fadd_rn(a, b.y), p));
        n2 = __fadd_rn(n2, __fmul_rn(__fadd_rn(a, b.z), p));
        n3 = __fadd_rn(n3, __fmul_rn(__fadd_rn(a, b.w), p));
    }
    float mn = __uint_as_float(g_nmin);
    float mx = __uint_as_float(g_nmax);
    float d = __fsub_rn(mx, mn);
    uchar4 v;
    v.x = (unsigned char)(int)rintf(__fmul_rn(__fdiv_rn(__fsub_rn(n0, mn), d), 15.0f));
    v.y = (unsigned char)(int)rintf(__fmul_rn(__fdiv_rn(__fsub_rn(n1, mn), d), 15.0f));
    v.z = (unsigned char)(int)rintf(__fmul_rn(__fdiv_rn(__fsub_rn(n2, mn), d), 15.0f));
    v.w = (unsigned char)(int)rintf(__fmul_rn(__fdiv_rn(__fsub_rn(n3, mn), d), 15.0f));
    ((uchar4*)g_idx)[g] = v;
}

// Separable count-space box blur; transposed dot (thread = 1 batch x 4 pixels x 2 halves),
// halves processed fully sequentially to keep register pressure low.
template <bool WRITE>
__global__ void __launch_bounds__(256, 4) k_blur(const float* __restrict__ colors,
                                                 float* __restrict__ out) {
    __shared__ unsigned char tile[12][36];
    __shared__ __align__(16) float colB4[NB * 17 * 4];   // [b][k] float4, stride 17
    __shared__ __align__(16) uint4 vcnt[8][40];          // vertical counts
    __shared__ __align__(16) uint4 hbufp[292];           // padded idx p + p/8
    __shared__ float smn[8], smx[8];

    int tx = threadIdx.x, ty = threadIdx.y;              // blockDim = (32, 8)
    int t = ty * 32 + tx;

    // palette -> smem: colB4[(b*17 + k)*4 + c], c<3 real, c=3 pad
    for (int idx = t; idx < NB * NCOL * 4; idx += 256) {
        int b = idx >> 6, rem = idx & 63, k = rem >> 2, c = rem & 3;
        colB4[(b * 17 + k) * 4 + c] = (c < 3) ? colors[b * 48 + k * 3 + c] : 0.0f;
    }

    int bi0 = blockIdx.y * 8, bj0 = blockIdx.x * 32;
    for (int q = t; q < 12 * 36; q += 256) {
        int r = q / 36, cc = q % 36;
        int gi = bi0 + r - 2, gj = bj0 + cc - 2;
        unsigned char v = 16;  // border sentinel: no count
        if ((unsigned)gi < (unsigned)NW && (unsigned)gj < (unsigned)NW)
            v = g_idx[gi * NW + gj];
        tile[r][cc] = v;
    }
    __syncthreads();

    // Phase 2: vertical 5-tap packed counts (288 entries, u8 fields in 4 x u32)
    for (int e = t; e < 8 * 36; e += 256) {
        int r = e / 36, c = e % 36;
        unsigned h0 = 0, h1 = 0, h2 = 0, h3 = 0;
        #pragma unroll
        for (int dy = 0; dy < 5; dy++) {
            int k = tile[r + dy][c];
            unsigned one = 1u << ((k & 3) * 8);
            unsigned w = (unsigned)k >> 2;
            h0 += (w == 0) ? one : 0u;
            h1 += (w == 1) ? one : 0u;
            h2 += (w == 2) ? one : 0u;
            h3 += (w == 3) ? one : 0u;
        }
        vcnt[r][c] = make_uint4(h0, h1, h2, h3);
    }
    __syncthreads();

    // Phase 3: horizontal 5-tap sum for own pixel -> hbuf (padded: idx = p + p/8)
    {
        uint4 h = vcnt[ty][tx];
        #pragma unroll
        for (int dx = 1; dx < 5; dx++) {
            uint4 v = vcnt[ty][tx + dx];
            h.x += v.x; h.y += v.y; h.z += v.z; h.w += v.w;
        }
        hbufp[t + (t >> 3)] = h;
    }
    __syncthreads();

    // Phase 4 (dot): thread = batch b = t&7, pixel group pg = t>>3 (2 halves x 4 px)
    int b = t & 7, pg = t >> 3;
    const float4* colp = (const float4*)&colB4[b * 17 * 4];
    const unsigned long long bias2 = pack2(-8388608.0f);

    if constexpr (!WRITE) {
        float lmn = FLT_MAX, lmx = 0.0f;
        #pragma unroll
        for (int half = 0; half < 2; half++) {
            uint4 hh0 = hbufp[pg * 9 + half * 4 + 0];
            uint4 hh1 = hbufp[pg * 9 + half * 4 + 1];
            uint4 hh2 = hbufp[pg * 9 + half * 4 + 2];
            uint4 hh3 = hbufp[pg * 9 + half * 4 + 3];
            unsigned long long acc[6];
            #pragma unroll
            for (int q = 0; q < 6; q++) acc[q] = 0ull;

            #pragma unroll
            for (int k = 0; k < NCOL; k++) {
                float4 col = colp[k];
                unsigned long long cx = pack2(col.x);
                unsigned long long cy = pack2(col.y);
                unsigned long long cz = pack2(col.z);
                unsigned sel = 0x7440u | (unsigned)(k & 3);
                unsigned w0, w1, w2, w3;
                if ((k >> 2) == 0)      { w0 = hh0.x; w1 = hh1.x; w2 = hh2.x; w3 = hh3.x; }
                else if ((k >> 2) == 1) { w0 = hh0.y; w1 = hh1.y; w2 = hh2.y; w3 = hh3.y; }
                else if ((k >> 2) == 2) { w0 = hh0.z; w1 = hh1.z; w2 = hh2.z; w3 = hh3.z; }
                else                    { w0 = hh0.w; w1 = hh1.w; w2 = hh2.w; w3 = hh3.w; }
                unsigned long long c01 = add2(pkbits(prmtf(w0, sel), prmtf(w1, sel)), bias2);
                unsigned long long c23 = add2(pkbits(prmtf(w2, sel), prmtf(w3, sel)), bias2);
                fma2(acc[0], c01, cx); fma2(acc[1], c01, cy); fma2(acc[2], c01, cz);
                fma2(acc[3], c23, cx); fma2(acc[4], c23, cy); fma2(acc[5], c23, cz);
            }
            #pragma unroll
            for (int q = 0; q < 6; q++) {
                float a, bb; unpack2(acc[q], a, bb);
                lmn = fminf(lmn, fminf(a, bb));
                lmx = fmaxf(lmx, fmaxf(a, bb));
            }
        }
        lmn *= 0.04f; lmx *= 0.04f;
        #pragma unroll
        for (int off = 16; off; off >>= 1) {
            lmn = fminf(lmn, __shfl_xor_sync(0xffffffffu, lmn, off));
            lmx = fmaxf(lmx, __shfl_xor_sync(0xffffffffu, lmx, off));
        }
        int lane = t & 31, w = t >> 5;
        if (lane == 0) { smn[w] = lmn; smx[w] = lmx; }
        __syncthreads();
        if (t == 0) {
            lmn = smn[0]; lmx = smx[0];
            #pragma unroll
            for (int q = 1; q < 8; q++) { lmn = fminf(lmn, smn[q]); lmx = fmaxf(lmx, smx[q]); }
            atomicMin(&g_omin, __float_as_uint(lmn));
            atomicMax(&g_omax, __float_as_uint(lmx));
        }
    } else {
        __shared__ __align__(16) float stage3[24 * 260];   // dedicated (no union)

        float mnv = __uint_as_float(g_omin);
        float mxv = __uint_as_float(g_omax);
        float inv = 1.0f / (mxv - mnv);
        unsigned long long kwi2 = pack2(0.04f * inv);
        unsigned long long off2 = pack2(-mnv * inv);

        #pragma unroll
        for (int half = 0; half < 2; half++) {
            uint4 hh0 = hbufp[pg * 9 + half * 4 + 0];
            uint4 hh1 = hbufp[pg * 9 + half * 4 + 1];
            uint4 hh2 = hbufp[pg * 9 + half * 4 + 2];
            uint4 hh3 = hbufp[pg * 9 + half * 4 + 3];
            unsigned long long acc[6];
            #pragma unroll
            for (int q = 0; q < 6; q++) acc[q] = 0ull;

            #pragma unroll
            for (int k = 0; k < NCOL; k++) {
                float4 col = colp[k];
                unsigned long long cx = pack2(col.x);
                unsigned long long cy = pack2(col.y);
                unsigned long long cz = pack2(col.z);
                unsigned sel = 0x7440u | (unsigned)(k & 3);
                unsigned w0, w1, w2, w3;
                if ((k >> 2) == 0)      { w0 = hh0.x; w1 = hh1.x; w2 = hh2.x; w3 = hh3.x; }
                else if ((k >> 2) == 1) { w0 = hh0.y; w1 = hh1.y; w2 = hh2.y; w3 = hh3.y; }
                else if ((k >> 2) == 2) { w0 = hh0.z; w1 = hh1.z; w2 = hh2.z; w3 = hh3.z; }
                else                    { w0 = hh0.w; w1 = hh1.w; w2 = hh2.w; w3 = hh3.w; }
                unsigned long long c01 = add2(pkbits(prmtf(w0, sel), prmtf(w1, sel)), bias2);
                unsigned long long c23 = add2(pkbits(prmtf(w2, sel), prmtf(w3, sel)), bias2);
                fma2(acc[0], c01, cx); fma2(acc[1], c01, cy); fma2(acc[2], c01, cz);
                fma2(acc[3], c23, cx); fma2(acc[4], c23, cy); fma2(acc[5], c23, cz);
            }

            // scale + store this half immediately (frees registers)
            #pragma unroll
            for (int q = 0; q < 6; q++) {
                unsigned long long v = fmascale2(acc[q], kwi2, off2);
                float a, bb; unpack2(v, a, bb);
                int pair = q / 3, ch = q % 3;
                int p0 = pg * 8 + half * 4 + pair * 2;
                stage3[(b * 3 + ch) * 260 + p0]     = a;
                stage3[(b * 3 + ch) * 260 + p0 + 1] = bb;
            }
        }
        __syncthreads();
        // coalesced output: 1536 float4 chunks, 6 per thread
        #pragma unroll
        for (int s = 0; s < 6; s++) {
            int m2 = t + 256 * s;
            int ob = m2 / 192;
            int rm = m2 % 192;
            int r = rm / 24, c4 = rm % 24;
            float4 v;
            float* vp = (float*)&v;
            #pragma unroll
            for (int u = 0; u < 4; u++) {
                int f = 4 * c4 + u;
                vp[u] = stage3[(ob * 3 + (f % 3)) * 260 + r * 32 + (f / 3)];
            }
            long long base = (((long long)ob * NW + (bi0 + r)) * NW + bj0) * 3 + 4 * c4;
            *(float4*)&out[base] = v;
        }
    }
}

extern "C" void kernel_launch(void* const* d_in, const int* in_sizes, int n_in,
                              void* d_out, int out_size) {
    (void)in_sizes; (void)n_in; (void)out_size;
    const float* colors = (const float*)d_in[0];
    float* out = (float*)d_out;

    k_octaves<<<NOCT, NW>>>();
    k_nminmax<<<(NW * NW / 4) / 256, 256>>>();
    k_makeidx<<<(NW * NW / 4) / 256, 256>>>();

    dim3 blk(32, 8);
    dim3 grd(NW / 32, NW / 8);
    k_blur<false><<<grd, blk>>>(colors, nullptr);
    k_blur<true><<<grd, blk>>>(colors, out);
}